// round 3
// baseline (speedup 1.0000x reference)
#include <cuda_runtime.h>
#include <math.h>

// Problem constants (GATLSTMCell: B=2, N=20000, E=320000, IN=64, HID=64, C=256, K=128)
constexpr int NN  = 20000;
constexpr int BB  = 2;
constexpr int EE  = 320000;
constexpr int CC  = 256;
constexpr int KD  = 128;
constexpr int HID = 64;

// ---- device scratch (static: no allocations allowed) ----
__device__ float g_xw[(size_t)BB * NN * CC];   // 40.96 MB
__device__ float g_as[BB * NN];
__device__ float g_ad[BB * NN];
__device__ int   g_counts[NN];
__device__ int   g_offsets[NN + 1];
__device__ int   g_cursor[NN];
__device__ int   g_csr[EE + NN];
__device__ int   g_idx64;

// ---------------------------------------------------------------------------
// K-detect: decide whether edge_index is int64 or int32 (JAX x64 quirk).
// For int64 with values < 2^31, the odd 32-bit words are zero; for int32 they
// are random node ids.
__global__ void detect_k(const int* __restrict__ e, int nwords) {
    if (threadIdx.x == 0 && blockIdx.x == 0) {
        int any = 0;
        int lim = nwords < 512 ? nwords : 512;
        for (int i = 1; i < lim; i += 2) any |= e[i];
        g_idx64 = (any == 0) ? 1 : 0;
    }
}

// K0: zero the histogram
__global__ void init_k() {
    int i = blockIdx.x * blockDim.x + threadIdx.x;
    if (i < NN) g_counts[i] = 0;
}

// ---------------------------------------------------------------------------
// K1: xw[b,n,c] = sum_f x[b,n,f] * W[c,f],  x = concat(input, h_cur)
// 64x64 tile, K=128 as two 64-chunks (chunk0 = input, chunk1 = h_cur).
// 256 threads = 16x16, each computes a 4x4 micro-tile. Static smem (~33 KB).
__global__ void __launch_bounds__(256) gemm_k(const float* __restrict__ inp,
                                              const float* __restrict__ hcur,
                                              const float* __restrict__ W) {
    __shared__ float As[64][65];
    __shared__ float Bs[64][65];

    const int t  = threadIdx.x;
    const int b  = blockIdx.z;
    const int n0 = blockIdx.x * 64;
    const int c0 = blockIdx.y * 64;

    const int col4 = (t & 15) * 4;   // 0..60
    const int rowg = t >> 4;         // 0..15

    const int tx = t & 15;
    const int ty = t >> 4;

    float acc[4][4];
    #pragma unroll
    for (int i = 0; i < 4; i++)
        #pragma unroll
        for (int j = 0; j < 4; j++) acc[i][j] = 0.f;

    #pragma unroll
    for (int kc = 0; kc < 2; kc++) {
        const float* A = (kc == 0) ? inp : hcur;
        // Load A tile: 64 nodes x 64 feats (4 passes of 16 rows)
        #pragma unroll
        for (int pass = 0; pass < 4; pass++) {
            int rl = pass * 16 + rowg;
            int node = n0 + rl;
            float4 v = make_float4(0.f, 0.f, 0.f, 0.f);
            if (node < NN)
                v = *reinterpret_cast<const float4*>(A + ((size_t)(b * NN + node)) * 64 + col4);
            As[rl][col4 + 0] = v.x; As[rl][col4 + 1] = v.y;
            As[rl][col4 + 2] = v.z; As[rl][col4 + 3] = v.w;
        }
        // Load B tile: 64 W rows x 64 k
        #pragma unroll
        for (int pass = 0; pass < 4; pass++) {
            int rl = pass * 16 + rowg;
            float4 v = *reinterpret_cast<const float4*>(W + (size_t)(c0 + rl) * KD + kc * 64 + col4);
            Bs[rl][col4 + 0] = v.x; Bs[rl][col4 + 1] = v.y;
            Bs[rl][col4 + 2] = v.z; Bs[rl][col4 + 3] = v.w;
        }
        __syncthreads();

        #pragma unroll 8
        for (int k = 0; k < 64; k++) {
            float a[4], bv[4];
            #pragma unroll
            for (int p = 0; p < 4; p++) a[p]  = As[ty * 4 + p][k];
            #pragma unroll
            for (int p = 0; p < 4; p++) bv[p] = Bs[tx * 4 + p][k];
            #pragma unroll
            for (int i = 0; i < 4; i++)
                #pragma unroll
                for (int j = 0; j < 4; j++) acc[i][j] = fmaf(a[i], bv[j], acc[i][j]);
        }
        __syncthreads();
    }

    #pragma unroll
    for (int i = 0; i < 4; i++) {
        int node = n0 + ty * 4 + i;
        if (node < NN) {
            float4 v = make_float4(acc[i][0], acc[i][1], acc[i][2], acc[i][3]);
            *reinterpret_cast<float4*>(g_xw + ((size_t)(b * NN + node)) * CC + c0 + tx * 4) = v;
        }
    }
}

// ---------------------------------------------------------------------------
// K2: a_s[b,n] = xw[b,n,:] . att_src ; a_d likewise.  One warp per (b,n).
__global__ void __launch_bounds__(256) attn_k(const float* __restrict__ att_s,
                                              const float* __restrict__ att_d) {
    int wid  = (blockIdx.x * blockDim.x + threadIdx.x) >> 5;
    int lane = threadIdx.x & 31;
    if (wid >= BB * NN) return;
    const float* row = g_xw + (size_t)wid * CC;
    float s = 0.f, d = 0.f;
    #pragma unroll
    for (int k = 0; k < 8; k++) {
        int c = lane + 32 * k;
        float v = row[c];
        s = fmaf(v, att_s[c], s);
        d = fmaf(v, att_d[c], d);
    }
    #pragma unroll
    for (int o = 16; o > 0; o >>= 1) {
        s += __shfl_down_sync(0xffffffffu, s, o);
        d += __shfl_down_sync(0xffffffffu, d, o);
    }
    if (lane == 0) { g_as[wid] = s; g_ad[wid] = d; }
}

// ---------------------------------------------------------------------------
// Index helpers: dtype decided at runtime by detect_k.
__device__ __forceinline__ int load_index(const void* p, int i, int is64) {
    return is64 ? (int)((const long long*)p)[i] : ((const int*)p)[i];
}

// K3: histogram of dst
__global__ void hist_k(const void* __restrict__ edges, int E) {
    int i = blockIdx.x * blockDim.x + threadIdx.x;
    if (i >= E) return;
    int is64 = g_idx64;
    int d = load_index(edges, E + i, is64);
    if ((unsigned)d < (unsigned)NN) atomicAdd(&g_counts[d], 1);
}

// K4: exclusive scan of (counts+1) -> offsets, cursor.  Single block.
__global__ void scan_k() {
    __shared__ int s[1024];
    int carry = 0;
    for (int base = 0; base < NN; base += 1024) {
        int idx = base + threadIdx.x;
        int v = (idx < NN) ? (g_counts[idx] + 1) : 0;
        s[threadIdx.x] = v;
        __syncthreads();
        for (int off = 1; off < 1024; off <<= 1) {
            int tv = (threadIdx.x >= off) ? s[threadIdx.x - off] : 0;
            __syncthreads();
            s[threadIdx.x] += tv;
            __syncthreads();
        }
        int incl = s[threadIdx.x];
        if (idx < NN) {
            g_offsets[idx + 1] = carry + incl;
            g_cursor[idx]      = carry + incl - v;
        }
        if (idx == 0) g_offsets[0] = 0;
        int tot = s[1023];
        __syncthreads();
        carry += tot;
    }
}

// K5: scatter edges into CSR slots (last slot of each segment reserved = self loop)
__global__ void fill_k(const void* __restrict__ edges, int E) {
    int i = blockIdx.x * blockDim.x + threadIdx.x;
    if (i >= E) return;
    int is64 = g_idx64;
    int srcv = load_index(edges, i, is64);
    int d    = load_index(edges, E + i, is64);
    if ((unsigned)d < (unsigned)NN && (unsigned)srcv < (unsigned)NN) {
        int pos = atomicAdd(&g_cursor[d], 1);
        g_csr[pos] = srcv;
    }
}

// ---------------------------------------------------------------------------
// K6: per-(dst,batch) warp: softmax-weighted aggregation + LSTM gates.
// (segment-max subtraction is redundant: |e| is O(4), exp() is safe)
__global__ void __launch_bounds__(256) agg_k(const float* __restrict__ bias,
                                             const float* __restrict__ c_cur,
                                             float* __restrict__ out) {
    int wid  = (blockIdx.x * blockDim.x + threadIdx.x) >> 5;
    int lane = threadIdx.x & 31;
    if (wid >= BB * NN) return;
    int b = wid / NN;
    int n = wid - b * NN;

    int off0 = g_offsets[n];
    int off1 = g_offsets[n + 1];

    float adn = g_ad[wid];
    const float* as_b = g_as + b * NN;
    const float* xw_b = g_xw + (size_t)b * NN * CC;

    float acc[8];
    #pragma unroll
    for (int k = 0; k < 8; k++) acc[k] = 0.f;
    float S = 0.f;

    for (int i = off0; i < off1; i++) {
        int s = (i == off1 - 1) ? n : g_csr[i];
        float e = as_b[s] + adn;
        e = (e >= 0.f) ? e : 0.2f * e;      // LeakyReLU(0.2)
        float w = __expf(e);
        S += w;
        const float* row = xw_b + (size_t)s * CC + lane;
        #pragma unroll
        for (int k = 0; k < 8; k++) acc[k] = fmaf(w, row[32 * k], acc[k]);
    }
    float inv = 1.0f / S;

    size_t base = (size_t)wid * HID;
    #pragma unroll
    for (int k2 = 0; k2 < 2; k2++) {
        int j = lane + 32 * k2;
        float xi = fmaf(acc[0 + k2], inv, bias[j]);
        float xf = fmaf(acc[2 + k2], inv, bias[64 + j]);
        float xo = fmaf(acc[4 + k2], inv, bias[128 + j]);
        float xg = fmaf(acc[6 + k2], inv, bias[192 + j]);
        float iv = 1.f / (1.f + __expf(-xi));
        float fv = 1.f / (1.f + __expf(-xf));
        float ov = 1.f / (1.f + __expf(-xo));
        float gv = tanhf(xg);
        float cp = c_cur[base + j];
        float cn = fmaf(fv, cp, iv * gv);
        float hn = ov * tanhf(cn);
        out[base + j] = hn;                                  // h_next
        out[(size_t)BB * NN * HID + base + j] = cn;          // c_next
    }
}

// ---------------------------------------------------------------------------
extern "C" void kernel_launch(void* const* d_in, const int* in_sizes, int n_in,
                              void* d_out, int out_size) {
    const float* inp   = (const float*)d_in[0];
    const float* hcur  = (const float*)d_in[1];
    const float* ccur  = (const float*)d_in[2];
    const float* W     = (const float*)d_in[3];
    const float* att_s = (const float*)d_in[4];
    const float* att_d = (const float*)d_in[5];
    const float* bias  = (const float*)d_in[6];
    const void*  edges = d_in[7];
    float* out = (float*)d_out;

    int E = in_sizes[7] / 2;   // 320000 logical edges

    detect_k<<<1, 32>>>((const int*)edges, in_sizes[7]);
    init_k<<<(NN + 255) / 256, 256>>>();
    gemm_k<<<dim3((NN + 63) / 64, CC / 64, BB), 256>>>(inp, hcur, W);
    attn_k<<<(BB * NN * 32 + 255) / 256, 256>>>(att_s, att_d);
    hist_k<<<(E + 255) / 256, 256>>>(edges, E);
    scan_k<<<1, 1024>>>();
    fill_k<<<(E + 255) / 256, 256>>>(edges, E);
    agg_k<<<(BB * NN * 32 + 255) / 256, 256>>>(bias, ccur, out);
}

// round 5
// speedup vs baseline: 1.1442x; 1.1442x over previous
#include <cuda_runtime.h>
#include <math.h>

// GATLSTMCell: B=2, N=20000, E=320000, IN=64, HID=64, C=256, F=128
constexpr int NN  = 20000;
constexpr int BB  = 2;
constexpr int EE  = 320000;
constexpr int CC  = 256;
constexpr int FD  = 128;   // F_in = 64 input + 64 hidden
constexpr int HID = 64;

// ---- device scratch ----
__device__ float g_agg[(size_t)BB * NN * FD];    // 20.5 MB aggregated features
__device__ float g_conv[(size_t)BB * NN * CC];   // 41 MB conv output
__device__ float g_as[BB * NN];
__device__ float g_ad[BB * NN];
__device__ float g_vs[FD];
__device__ float g_vd[FD];
__device__ int   g_counts[NN];
__device__ int   g_offsets[NN + 1];
__device__ int   g_cursor[NN];
__device__ int   g_csr[EE + NN];
__device__ int   g_tex[20 * 256];
__device__ int   g_bsum[20];
__device__ int   g_bbase[20];
__device__ int   g_idx64;

// ---------------------------------------------------------------------------
__global__ void detect_k(const int* __restrict__ e, int nwords) {
    if (threadIdx.x == 0) {
        int any = 0;
        int lim = nwords < 512 ? nwords : 512;
        for (int i = 1; i < lim; i += 2) any |= e[i];
        g_idx64 = (any == 0) ? 1 : 0;
    }
}

__global__ void init_k() {
    int i = blockIdx.x * blockDim.x + threadIdx.x;
    if (i < NN) g_counts[i] = 0;
}

// v_s[f] = sum_c att_src[c] * W[c][f]   (one block, 128 threads, coalesced)
__global__ void vs_k(const float* __restrict__ W,
                     const float* __restrict__ att_s,
                     const float* __restrict__ att_d) {
    int f = threadIdx.x;
    float s = 0.f, d = 0.f;
    for (int c = 0; c < CC; c++) {
        float w = W[(size_t)c * FD + f];
        s = fmaf(att_s[c], w, s);
        d = fmaf(att_d[c], w, d);
    }
    g_vs[f] = s;
    g_vd[f] = d;
}

// a_s[b,n] = x[b,n,:].v_s  where x = concat(input, h).  One warp per (b,n).
__global__ void __launch_bounds__(256) asd_k(const float* __restrict__ inp,
                                             const float* __restrict__ hcur) {
    int wid  = (blockIdx.x * blockDim.x + threadIdx.x) >> 5;
    int lane = threadIdx.x & 31;
    if (wid >= BB * NN) return;
    size_t base = (size_t)wid * 64;
    float xi0 = inp[base + lane], xi1 = inp[base + lane + 32];
    float xh0 = hcur[base + lane], xh1 = hcur[base + lane + 32];
    float s = xi0 * g_vs[lane] + xi1 * g_vs[lane + 32]
            + xh0 * g_vs[64 + lane] + xh1 * g_vs[96 + lane];
    float d = xi0 * g_vd[lane] + xi1 * g_vd[lane + 32]
            + xh0 * g_vd[64 + lane] + xh1 * g_vd[96 + lane];
    #pragma unroll
    for (int o = 16; o > 0; o >>= 1) {
        s += __shfl_down_sync(0xffffffffu, s, o);
        d += __shfl_down_sync(0xffffffffu, d, o);
    }
    if (lane == 0) { g_as[wid] = s; g_ad[wid] = d; }
}

// ---------------------------------------------------------------------------
__device__ __forceinline__ int load_index(const void* p, int i, int is64) {
    return is64 ? (int)((const long long*)p)[i] : ((const int*)p)[i];
}

__global__ void hist_k(const void* __restrict__ edges, int E) {
    int i = blockIdx.x * blockDim.x + threadIdx.x;
    if (i >= E) return;
    int d = load_index(edges, E + i, g_idx64);
    if ((unsigned)d < (unsigned)NN) atomicAdd(&g_counts[d], 1);
}

// 3-phase exclusive scan of (counts+1) over 20 blocks x 1024 elems
__global__ void scan1_k() {
    __shared__ int wsum[8];
    int blk = blockIdx.x, t = threadIdx.x, lane = t & 31, w = t >> 5;
    int i0 = blk * 1024 + t * 4;
    int tsum = 0;
    #pragma unroll
    for (int q = 0; q < 4; q++) tsum += (i0 + q < NN) ? (g_counts[i0 + q] + 1) : 0;
    int incl = tsum;
    #pragma unroll
    for (int o = 1; o < 32; o <<= 1) {
        int x = __shfl_up_sync(0xffffffffu, incl, o);
        if (lane >= o) incl += x;
    }
    if (lane == 31) wsum[w] = incl;
    __syncthreads();
    if (t == 0) {
        int run = 0;
        #pragma unroll
        for (int i = 0; i < 8; i++) { int x = wsum[i]; wsum[i] = run; run += x; }
        g_bsum[blk] = run;
    }
    __syncthreads();
    g_tex[blk * 256 + t] = wsum[w] + incl - tsum;
}

__global__ void scan2_k() {
    int lane = threadIdx.x;
    int v = (lane < 20) ? g_bsum[lane] : 0;
    int incl = v;
    #pragma unroll
    for (int o = 1; o < 32; o <<= 1) {
        int x = __shfl_up_sync(0xffffffffu, incl, o);
        if (lane >= o) incl += x;
    }
    if (lane < 20) g_bbase[lane] = incl - v;
}

__global__ void scan3_k() {
    int blk = blockIdx.x, t = threadIdx.x;
    int i0 = blk * 1024 + t * 4;
    int off = g_bbase[blk] + g_tex[blk * 256 + t];
    #pragma unroll
    for (int q = 0; q < 4; q++) {
        int idx = i0 + q;
        if (idx < NN) {
            int v = g_counts[idx] + 1;
            g_offsets[idx] = off;
            g_cursor[idx]  = off;
            if (idx == NN - 1) g_offsets[NN] = off + v;
            off += v;
        }
    }
}

__global__ void fill_k(const void* __restrict__ edges, int E) {
    int i = blockIdx.x * blockDim.x + threadIdx.x;
    if (i >= E) return;
    int is64 = g_idx64;
    int s = load_index(edges, i, is64);
    int d = load_index(edges, E + i, is64);
    if ((unsigned)d < (unsigned)NN && (unsigned)s < (unsigned)NN) {
        int pos = atomicAdd(&g_cursor[d], 1);
        g_csr[pos] = s;
    }
}

// ---------------------------------------------------------------------------
// Aggregate in 128-feature space: agg[b,n,f] = (1/S) sum_e w_e * x[src,f]
// One warp per (dst,batch); lane covers f = lane, +32, +64, +96.
__global__ void __launch_bounds__(256) agg_k(const float* __restrict__ inp,
                                             const float* __restrict__ hcur) {
    int wid  = (blockIdx.x * blockDim.x + threadIdx.x) >> 5;
    int lane = threadIdx.x & 31;
    if (wid >= BB * NN) return;
    int b = wid / NN;
    int n = wid - b * NN;

    int off0 = g_offsets[n];
    int off1 = g_offsets[n + 1];

    float adn = g_ad[wid];
    const float* as_b = g_as + b * NN;
    size_t bbase = (size_t)b * NN * 64;

    float a0 = 0.f, a1 = 0.f, a2 = 0.f, a3 = 0.f, S = 0.f;

    for (int i = off0; i < off1; i++) {
        int s = (i == off1 - 1) ? n : g_csr[i];
        float e = as_b[s] + adn;
        e = (e >= 0.f) ? e : 0.2f * e;         // LeakyReLU(0.2)
        float w = __expf(e);
        S += w;
        size_t rb = bbase + (size_t)s * 64;
        a0 = fmaf(w, inp[rb + lane], a0);
        a1 = fmaf(w, inp[rb + lane + 32], a1);
        a2 = fmaf(w, hcur[rb + lane], a2);
        a3 = fmaf(w, hcur[rb + lane + 32], a3);
    }
    float inv = 1.0f / S;
    float* o = g_agg + (size_t)wid * FD;
    o[lane]      = a0 * inv;
    o[lane + 32] = a1 * inv;
    o[lane + 64] = a2 * inv;
    o[lane + 96] = a3 * inv;
}

// ---------------------------------------------------------------------------
// conv[b,n,c] = sum_f agg[b,n,f] * W[c,f].  128x128 tile, 8x8 micro-tile.
// Transposed smem [k][row], pad 132 (528 B: 16B-aligned rows for LDS.128).
__global__ void __launch_bounds__(256, 2) gemm_k(const float* __restrict__ W) {
    __shared__ float As[32][132];
    __shared__ float Bs[32][132];

    const int t  = threadIdx.x;
    const int b  = blockIdx.z;
    const int n0 = blockIdx.x * 128;
    const int c0 = blockIdx.y * 128;
    const int tx = t & 15;
    const int ty = t >> 4;

    float acc[8][8];
    #pragma unroll
    for (int i = 0; i < 8; i++)
        #pragma unroll
        for (int j = 0; j < 8; j++) acc[i][j] = 0.f;

    #pragma unroll
    for (int kc = 0; kc < 4; kc++) {
        // load A tile: 128 nodes x 32 k  (1024 float4, 4 per thread)
        #pragma unroll
        for (int pass = 0; pass < 4; pass++) {
            int idx  = pass * 256 + t;       // 0..1023
            int f4   = idx & 7;              // k-group
            int row  = idx >> 3;             // node 0..127
            int k    = f4 * 4;
            float4 v = make_float4(0.f, 0.f, 0.f, 0.f);
            int node = n0 + row;
            if (node < NN)
                v = *reinterpret_cast<const float4*>(
                        g_agg + ((size_t)(b * NN + node)) * FD + kc * 32 + k);
            As[k + 0][row] = v.x; As[k + 1][row] = v.y;
            As[k + 2][row] = v.z; As[k + 3][row] = v.w;
        }
        // load B tile: 128 c-rows x 32 k
        #pragma unroll
        for (int pass = 0; pass < 4; pass++) {
            int idx = pass * 256 + t;
            int f4  = idx & 7;
            int row = idx >> 3;              // c 0..127
            int k   = f4 * 4;
            float4 v = *reinterpret_cast<const float4*>(
                           W + (size_t)(c0 + row) * FD + kc * 32 + k);
            Bs[k + 0][row] = v.x; Bs[k + 1][row] = v.y;
            Bs[k + 2][row] = v.z; Bs[k + 3][row] = v.w;
        }
        __syncthreads();

        #pragma unroll
        for (int k = 0; k < 32; k++) {
            float4 av0 = *reinterpret_cast<const float4*>(&As[k][ty * 8]);
            float4 av1 = *reinterpret_cast<const float4*>(&As[k][ty * 8 + 4]);
            float4 bv0 = *reinterpret_cast<const float4*>(&Bs[k][tx * 8]);
            float4 bv1 = *reinterpret_cast<const float4*>(&Bs[k][tx * 8 + 4]);
            float a[8]  = {av0.x, av0.y, av0.z, av0.w, av1.x, av1.y, av1.z, av1.w};
            float bb[8] = {bv0.x, bv0.y, bv0.z, bv0.w, bv1.x, bv1.y, bv1.z, bv1.w};
            #pragma unroll
            for (int i = 0; i < 8; i++)
                #pragma unroll
                for (int j = 0; j < 8; j++) acc[i][j] = fmaf(a[i], bb[j], acc[i][j]);
        }
        __syncthreads();
    }

    #pragma unroll
    for (int i = 0; i < 8; i++) {
        int node = n0 + ty * 8 + i;
        if (node < NN) {
            float* dst = g_conv + ((size_t)(b * NN + node)) * CC + c0 + tx * 8;
            *reinterpret_cast<float4*>(dst)     = make_float4(acc[i][0], acc[i][1], acc[i][2], acc[i][3]);
            *reinterpret_cast<float4*>(dst + 4) = make_float4(acc[i][4], acc[i][5], acc[i][6], acc[i][7]);
        }
    }
}

// ---------------------------------------------------------------------------
// LSTM epilogue: thread per (b,n,j)
__global__ void __launch_bounds__(256) lstm_k(const float* __restrict__ bias,
                                              const float* __restrict__ c_cur,
                                              float* __restrict__ out) {
    int gid = blockIdx.x * blockDim.x + threadIdx.x;
    if (gid >= BB * NN * HID) return;
    int bn = gid >> 6;
    int j  = gid & 63;
    const float* cv = g_conv + (size_t)bn * CC;
    float xi = cv[j]       + bias[j];
    float xf = cv[64 + j]  + bias[64 + j];
    float xo = cv[128 + j] + bias[128 + j];
    float xg = cv[192 + j] + bias[192 + j];
    float iv = 1.f / (1.f + __expf(-xi));
    float fv = 1.f / (1.f + __expf(-xf));
    float ov = 1.f / (1.f + __expf(-xo));
    float gv = tanhf(xg);
    float cn = fmaf(fv, c_cur[gid], iv * gv);
    out[gid] = ov * tanhf(cn);
    out[(size_t)BB * NN * HID + gid] = cn;
}

// ---------------------------------------------------------------------------
extern "C" void kernel_launch(void* const* d_in, const int* in_sizes, int n_in,
                              void* d_out, int out_size) {
    const float* inp   = (const float*)d_in[0];
    const float* hcur  = (const float*)d_in[1];
    const float* ccur  = (const float*)d_in[2];
    const float* W     = (const float*)d_in[3];
    const float* att_s = (const float*)d_in[4];
    const float* att_d = (const float*)d_in[5];
    const float* bias  = (const float*)d_in[6];
    const void*  edges = d_in[7];
    float* out = (float*)d_out;

    int E = in_sizes[7] / 2;

    detect_k<<<1, 32>>>((const int*)edges, in_sizes[7]);
    init_k<<<(NN + 255) / 256, 256>>>();
    vs_k<<<1, FD>>>(W, att_s, att_d);
    asd_k<<<(BB * NN * 32 + 255) / 256, 256>>>(inp, hcur);
    hist_k<<<(E + 255) / 256, 256>>>(edges, E);
    scan1_k<<<20, 256>>>();
    scan2_k<<<1, 32>>>();
    scan3_k<<<20, 256>>>();
    fill_k<<<(E + 255) / 256, 256>>>(edges, E);
    agg_k<<<(BB * NN * 32 + 255) / 256, 256>>>(inp, hcur);
    gemm_k<<<dim3((NN + 127) / 128, CC / 128, BB), 256>>>(W);
    lstm_k<<<(BB * NN * HID + 255) / 256, 256>>>(bias, ccur, out);
}

// round 6
// speedup vs baseline: 1.2903x; 1.1277x over previous
#include <cuda_runtime.h>
#include <math.h>

// GATLSTMCell: B=2, N=20000, E=320000, IN=64, HID=64, C=256, F=128
constexpr int NN  = 20000;
constexpr int BB  = 2;
constexpr int EE  = 320000;
constexpr int CC  = 256;
constexpr int FD  = 128;
constexpr int HID = 64;

// ---- device scratch ----
__device__ __align__(16) float g_agg[(size_t)BB * NN * FD];
__device__ __align__(16) float g_conv[(size_t)BB * NN * CC];
__device__ float g_as[BB * NN];
__device__ float g_ad[BB * NN];
__device__ __align__(16) float g_vs[FD];
__device__ __align__(16) float g_vd[FD];
__device__ int   g_counts[NN];
__device__ int   g_offsets[NN + 1];
__device__ int   g_cursor[NN];
__device__ int   g_csr[EE + NN];
__device__ int   g_idx64;

// f32x2 packed-FMA helpers (Blackwell; ptxas won't emit FFMA2 from C++)
#define FMA2(d_, a_, b_) \
    asm("fma.rn.f32x2 %0, %1, %2, %3;" : "=l"(d_) : "l"(a_), "l"(b_), "l"(d_))
#define PK2(d_, lo_, hi_) \
    asm("mov.b64 %0, {%1, %2};" : "=l"(d_) : "f"(lo_), "f"(hi_))
#define UPK2(lo_, hi_, s_) \
    asm("mov.b64 {%0, %1}, %2;" : "=f"(lo_), "=f"(hi_) : "l"(s_))

// ---------------------------------------------------------------------------
__global__ void detect_k(const int* __restrict__ e, int nwords) {
    int lane = threadIdx.x;
    int lim = nwords < 512 ? nwords : 512;
    int any = 0;
    for (int i = 1 + 2 * lane; i < lim; i += 64) any |= e[i];
    any = __reduce_or_sync(0xffffffffu, any);
    if (lane == 0) g_idx64 = (any == 0) ? 1 : 0;
}

// blocks 0..78: zero counts; block 79: v_s = W^T att_src, v_d = W^T att_dst
__global__ void __launch_bounds__(256) initvs_k(const float* __restrict__ W,
                                                const float* __restrict__ att_s,
                                                const float* __restrict__ att_d) {
    int t = threadIdx.x;
    if (blockIdx.x < 79) {
        int i = blockIdx.x * 256 + t;
        if (i < NN) g_counts[i] = 0;
        return;
    }
    __shared__ float sv[128], sd[128];
    int f  = t & 127;
    int hc = t >> 7;                 // half of c-range
    float s = 0.f, d = 0.f;
    for (int c = hc * 128; c < hc * 128 + 128; c++) {
        float w = W[(size_t)c * FD + f];
        s = fmaf(att_s[c], w, s);
        d = fmaf(att_d[c], w, d);
    }
    if (hc == 0) { sv[f] = s; sd[f] = d; }
    __syncthreads();
    if (hc == 1) { g_vs[f] = sv[f] + s; g_vd[f] = sd[f] + d; }
}

// a_s[b,n] = x . v_s.  Warp per (b,n); lanes 0-15 read inp float4, 16-31 hcur.
__global__ void __launch_bounds__(256) asd_k(const float* __restrict__ inp,
                                             const float* __restrict__ hcur) {
    int wid  = (blockIdx.x * blockDim.x + threadIdx.x) >> 5;
    int lane = threadIdx.x & 31;
    if (wid >= BB * NN) return;
    const float* basep = (lane & 16) ? hcur : inp;
    int f0 = (lane & 16) * 4 + (lane & 15) * 4;      // feature index 0..124
    float4 v  = *reinterpret_cast<const float4*>(basep + (size_t)wid * 64 + (lane & 15) * 4);
    float4 vs = *reinterpret_cast<const float4*>(g_vs + f0);
    float4 vd = *reinterpret_cast<const float4*>(g_vd + f0);
    float s = v.x * vs.x + v.y * vs.y + v.z * vs.z + v.w * vs.w;
    float d = v.x * vd.x + v.y * vd.y + v.z * vd.z + v.w * vd.w;
    #pragma unroll
    for (int o = 16; o > 0; o >>= 1) {
        s += __shfl_down_sync(0xffffffffu, s, o);
        d += __shfl_down_sync(0xffffffffu, d, o);
    }
    if (lane == 0) { g_as[wid] = s; g_ad[wid] = d; }
}

// ---------------------------------------------------------------------------
__device__ __forceinline__ int load_index(const void* p, int i, int is64) {
    return is64 ? (int)((const long long*)p)[i] : ((const int*)p)[i];
}

__global__ void hist_k(const void* __restrict__ edges, int E) {
    int i = blockIdx.x * blockDim.x + threadIdx.x;
    if (i >= E) return;
    int d = load_index(edges, E + i, g_idx64);
    if ((unsigned)d < (unsigned)NN) atomicAdd(&g_counts[d], 1);
}

// Single-block exclusive scan of (counts+1): 1024 threads x 20 items each.
__global__ void __launch_bounds__(1024) scan_k() {
    __shared__ int wsums[32];
    int t = threadIdx.x, lane = t & 31, w = t >> 5;
    int base = t * 20;
    int c[20];
    int sum = 0;
    #pragma unroll
    for (int q = 0; q < 20; q++) {
        int idx = base + q;
        int v = (idx < NN) ? (g_counts[idx] + 1) : 0;
        c[q] = sum;                  // local exclusive prefix
        sum += v;
    }
    int incl = sum;
    #pragma unroll
    for (int o = 1; o < 32; o <<= 1) {
        int x = __shfl_up_sync(0xffffffffu, incl, o);
        if (lane >= o) incl += x;
    }
    int wex = incl - sum;
    if (lane == 31) wsums[w] = incl;
    __syncthreads();
    if (w == 0) {
        int v2 = wsums[lane];
        int incl2 = v2;
        #pragma unroll
        for (int o = 1; o < 32; o <<= 1) {
            int x = __shfl_up_sync(0xffffffffu, incl2, o);
            if (lane >= o) incl2 += x;
        }
        wsums[lane] = incl2 - v2;
    }
    __syncthreads();
    int off = wsums[w] + wex;
    #pragma unroll
    for (int q = 0; q < 20; q++) {
        int idx = base + q;
        if (idx < NN) {
            int o = off + c[q];
            g_offsets[idx] = o;
            g_cursor[idx]  = o;
            if (idx == NN - 1) {
                int next = (q == 19) ? sum : c[q + 1];
                g_offsets[NN] = off + next;
            }
        }
    }
}

__global__ void fill_k(const void* __restrict__ edges, int E) {
    int i = blockIdx.x * blockDim.x + threadIdx.x;
    if (i >= E) return;
    int is64 = g_idx64;
    int s = load_index(edges, i, is64);
    int d = load_index(edges, E + i, is64);
    if ((unsigned)d < (unsigned)NN && (unsigned)s < (unsigned)NN) {
        int pos = atomicAdd(&g_cursor[d], 1);
        g_csr[pos] = s;
    }
}

// ---------------------------------------------------------------------------
// agg[b,n,:] = (1/S) sum_e w_e * x[src,:].  Warp per (dst,batch).
// Lanes 0-15 gather a float4 of inp, lanes 16-31 a float4 of hcur: one
// LDG.128 per lane per edge, 128 features covered.
__global__ void __launch_bounds__(256) agg_k(const float* __restrict__ inp,
                                             const float* __restrict__ hcur) {
    int wid  = (blockIdx.x * blockDim.x + threadIdx.x) >> 5;
    int lane = threadIdx.x & 31;
    if (wid >= BB * NN) return;
    int b = wid / NN;
    int n = wid - b * NN;

    int off0 = g_offsets[n];
    int off1 = g_offsets[n + 1];

    float adn = g_ad[wid];
    const float* as_b  = g_as + b * NN;
    const float* basep = ((lane & 16) ? hcur : inp) + (size_t)b * NN * 64 + (lane & 15) * 4;

    float4 acc = make_float4(0.f, 0.f, 0.f, 0.f);
    float S = 0.f;

    for (int i = off0; i < off1; i++) {
        int s = (i == off1 - 1) ? n : g_csr[i];
        float e = as_b[s] + adn;
        e = (e >= 0.f) ? e : 0.2f * e;        // LeakyReLU(0.2)
        float w = __expf(e);
        S += w;
        float4 v = *reinterpret_cast<const float4*>(basep + (size_t)s * 64);
        acc.x = fmaf(w, v.x, acc.x);
        acc.y = fmaf(w, v.y, acc.y);
        acc.z = fmaf(w, v.z, acc.z);
        acc.w = fmaf(w, v.w, acc.w);
    }
    float inv = 1.0f / S;
    float* o = g_agg + (size_t)wid * FD + (lane & 16) * 4 + (lane & 15) * 4;
    *reinterpret_cast<float4*>(o) =
        make_float4(acc.x * inv, acc.y * inv, acc.z * inv, acc.w * inv);
}

// ---------------------------------------------------------------------------
// conv[b,n,c] = sum_f agg[b,n,f] * W[c,f].  128x128 tile, 8x8 micro-tile,
// inner loop in packed f32x2 (FFMA2: 128 FMA/cyc/SM vs 64 for scalar FFMA).
__global__ void __launch_bounds__(256, 2) gemm_k(const float* __restrict__ W) {
    __shared__ float As[32][132];
    __shared__ float Bs[32][132];

    const int t  = threadIdx.x;
    const int b  = blockIdx.z;
    const int n0 = blockIdx.x * 128;
    const int c0 = blockIdx.y * 128;
    const int tx = t & 15;
    const int ty = t >> 4;

    unsigned long long acc2[8][4];
    #pragma unroll
    for (int i = 0; i < 8; i++)
        #pragma unroll
        for (int j = 0; j < 4; j++) acc2[i][j] = 0ull;

    #pragma unroll
    for (int kc = 0; kc < 4; kc++) {
        #pragma unroll
        for (int pass = 0; pass < 4; pass++) {
            int idx  = pass * 256 + t;
            int k    = (idx & 7) * 4;
            int row  = idx >> 3;
            float4 v = make_float4(0.f, 0.f, 0.f, 0.f);
            int node = n0 + row;
            if (node < NN)
                v = *reinterpret_cast<const float4*>(
                        g_agg + ((size_t)(b * NN + node)) * FD + kc * 32 + k);
            As[k + 0][row] = v.x; As[k + 1][row] = v.y;
            As[k + 2][row] = v.z; As[k + 3][row] = v.w;
        }
        #pragma unroll
        for (int pass = 0; pass < 4; pass++) {
            int idx = pass * 256 + t;
            int k   = (idx & 7) * 4;
            int row = idx >> 3;
            float4 v = *reinterpret_cast<const float4*>(
                           W + (size_t)(c0 + row) * FD + kc * 32 + k);
            Bs[k + 0][row] = v.x; Bs[k + 1][row] = v.y;
            Bs[k + 2][row] = v.z; Bs[k + 3][row] = v.w;
        }
        __syncthreads();

        #pragma unroll
        for (int k = 0; k < 32; k++) {
            float4 av0 = *reinterpret_cast<const float4*>(&As[k][ty * 8]);
            float4 av1 = *reinterpret_cast<const float4*>(&As[k][ty * 8 + 4]);
            float4 bv0 = *reinterpret_cast<const float4*>(&Bs[k][tx * 8]);
            float4 bv1 = *reinterpret_cast<const float4*>(&Bs[k][tx * 8 + 4]);
            unsigned long long b2[4];
            PK2(b2[0], bv0.x, bv0.y); PK2(b2[1], bv0.z, bv0.w);
            PK2(b2[2], bv1.x, bv1.y); PK2(b2[3], bv1.z, bv1.w);
            float a[8] = {av0.x, av0.y, av0.z, av0.w, av1.x, av1.y, av1.z, av1.w};
            #pragma unroll
            for (int i = 0; i < 8; i++) {
                unsigned long long a2;
                PK2(a2, a[i], a[i]);
                FMA2(acc2[i][0], a2, b2[0]);
                FMA2(acc2[i][1], a2, b2[1]);
                FMA2(acc2[i][2], a2, b2[2]);
                FMA2(acc2[i][3], a2, b2[3]);
            }
        }
        __syncthreads();
    }

    #pragma unroll
    for (int i = 0; i < 8; i++) {
        int node = n0 + ty * 8 + i;
        if (node < NN) {
            float r[8];
            UPK2(r[0], r[1], acc2[i][0]);
            UPK2(r[2], r[3], acc2[i][1]);
            UPK2(r[4], r[5], acc2[i][2]);
            UPK2(r[6], r[7], acc2[i][3]);
            float* dst = g_conv + ((size_t)(b * NN + node)) * CC + c0 + tx * 8;
            *reinterpret_cast<float4*>(dst)     = make_float4(r[0], r[1], r[2], r[3]);
            *reinterpret_cast<float4*>(dst + 4) = make_float4(r[4], r[5], r[6], r[7]);
        }
    }
}

// ---------------------------------------------------------------------------
// LSTM epilogue: thread per (b,n, 4 channels)  — all float4.
__global__ void __launch_bounds__(256) lstm_k(const float* __restrict__ bias,
                                              const float* __restrict__ c_cur,
                                              float* __restrict__ out) {
    int gid = blockIdx.x * blockDim.x + threadIdx.x;
    if (gid >= BB * NN * 16) return;
    int bn = gid >> 4;
    int j0 = (gid & 15) * 4;
    const float* cv = g_conv + (size_t)bn * CC;
    float4 xi = *reinterpret_cast<const float4*>(cv + j0);
    float4 xf = *reinterpret_cast<const float4*>(cv + 64 + j0);
    float4 xo = *reinterpret_cast<const float4*>(cv + 128 + j0);
    float4 xg = *reinterpret_cast<const float4*>(cv + 192 + j0);
    float4 bi = *reinterpret_cast<const float4*>(bias + j0);
    float4 bf = *reinterpret_cast<const float4*>(bias + 64 + j0);
    float4 bo = *reinterpret_cast<const float4*>(bias + 128 + j0);
    float4 bg = *reinterpret_cast<const float4*>(bias + 192 + j0);
    float4 cp = *reinterpret_cast<const float4*>(c_cur + (size_t)bn * HID + j0);

    float4 hn, cn;
    {
        float iv = 1.f / (1.f + __expf(-(xi.x + bi.x)));
        float fv = 1.f / (1.f + __expf(-(xf.x + bf.x)));
        float ov = 1.f / (1.f + __expf(-(xo.x + bo.x)));
        float gv = tanhf(xg.x + bg.x);
        cn.x = fmaf(fv, cp.x, iv * gv); hn.x = ov * tanhf(cn.x);
    }
    {
        float iv = 1.f / (1.f + __expf(-(xi.y + bi.y)));
        float fv = 1.f / (1.f + __expf(-(xf.y + bf.y)));
        float ov = 1.f / (1.f + __expf(-(xo.y + bo.y)));
        float gv = tanhf(xg.y + bg.y);
        cn.y = fmaf(fv, cp.y, iv * gv); hn.y = ov * tanhf(cn.y);
    }
    {
        float iv = 1.f / (1.f + __expf(-(xi.z + bi.z)));
        float fv = 1.f / (1.f + __expf(-(xf.z + bf.z)));
        float ov = 1.f / (1.f + __expf(-(xo.z + bo.z)));
        float gv = tanhf(xg.z + bg.z);
        cn.z = fmaf(fv, cp.z, iv * gv); hn.z = ov * tanhf(cn.z);
    }
    {
        float iv = 1.f / (1.f + __expf(-(xi.w + bi.w)));
        float fv = 1.f / (1.f + __expf(-(xf.w + bf.w)));
        float ov = 1.f / (1.f + __expf(-(xo.w + bo.w)));
        float gv = tanhf(xg.w + bg.w);
        cn.w = fmaf(fv, cp.w, iv * gv); hn.w = ov * tanhf(cn.w);
    }
    *reinterpret_cast<float4*>(out + (size_t)bn * HID + j0) = hn;
    *reinterpret_cast<float4*>(out + (size_t)BB * NN * HID + (size_t)bn * HID + j0) = cn;
}

// ---------------------------------------------------------------------------
extern "C" void kernel_launch(void* const* d_in, const int* in_sizes, int n_in,
                              void* d_out, int out_size) {
    const float* inp   = (const float*)d_in[0];
    const float* hcur  = (const float*)d_in[1];
    const float* ccur  = (const float*)d_in[2];
    const float* W     = (const float*)d_in[3];
    const float* att_s = (const float*)d_in[4];
    const float* att_d = (const float*)d_in[5];
    const float* bias  = (const float*)d_in[6];
    const void*  edges = d_in[7];
    float* out = (float*)d_out;

    int E = in_sizes[7] / 2;

    detect_k<<<1, 32>>>((const int*)edges, in_sizes[7]);
    initvs_k<<<80, 256>>>(W, att_s, att_d);
    asd_k<<<(BB * NN * 32 + 255) / 256, 256>>>(inp, hcur);
    hist_k<<<(E + 255) / 256, 256>>>(edges, E);
    scan_k<<<1, 1024>>>();
    fill_k<<<(E + 255) / 256, 256>>>(edges, E);
    agg_k<<<(BB * NN * 32 + 255) / 256, 256>>>(inp, hcur);
    gemm_k<<<dim3((NN + 127) / 128, CC / 128, BB), 256>>>(W);
    lstm_k<<<(BB * NN * 16 + 255) / 256, 256>>>(bias, ccur, out);
}